// round 5
// baseline (speedup 1.0000x reference)
#include <cuda_runtime.h>
#include <math.h>

#define Bn 512
#define Hn 1024
#define Sn 1024
#define Dn 128
#define Kn 32

// Output layout: [read (B*D)] [new_memory (B*S*D)] [weights (B*S)]
#define READ_OFF 0
#define MEM_OFF  (Bn*Dn)
#define W_OFF    (Bn*Dn + (size_t)Bn*Sn*Dn)

#define NCOPY 16384              // 16KB tiles of new_memory (1024 float4)
#define NZERO 128                // weights zero-fill tiles
#define NTOT  (NCOPY + NZERO)
#define NBLK  592                // 148 SMs x 4 resident CTAs
#define NWRK  128                // compute-role blocks

// Scratch + sync state (no allocation allowed -> device globals)
__device__ float4 g_query[Bn * (Dn/4)];
__device__ float4 g_value[Bn * (Dn/4)];
__device__ float  g_logits[Bn * Sn];
__device__ int    g_qv_done, g_lg_done, g_tick, g_drained;

#define DYN_SMEM 33792   // max(qv 32768, logits 33792, batch 4096)

__global__ void init_kernel()
{
    g_qv_done = 0; g_lg_done = 0; g_tick = 0; g_drained = 0;
}

// One copy tile off the global ticket. Returns false when exhausted.
// Internal block-uniform control; one __syncthreads per call.
__device__ __forceinline__ bool do_one_copy_tile(const float4* __restrict__ mem4,
                                                 float* __restrict__ out)
{
    __shared__ int s_t;
    if (threadIdx.x == 0) s_t = atomicAdd(&g_tick, 1);
    __syncthreads();
    int t = s_t;                      // into register before next overwrite
    if (t >= NTOT) return false;
    if (t < NCOPY) {
        const float4* s = mem4 + (size_t)t * 1024;
        float4*       d = (float4*)(out + MEM_OFF) + (size_t)t * 1024;
        #pragma unroll
        for (int j = 0; j < 4; j++) {
            int i = threadIdx.x + j * 256;
            __stcs(&d[i], __ldcs(&s[i]));
        }
    } else {
        float4* wz = (float4*)(out + W_OFF) + (size_t)(t - NCOPY) * 1024;
        float4 z = make_float4(0.f, 0.f, 0.f, 0.f);
        #pragma unroll
        for (int j = 0; j < 4; j++)
            __stcs(&wz[threadIdx.x + j * 256], z);
    }
    return true;
}

__global__ __launch_bounds__(256, 4)
void fused_kernel(const float* __restrict__ latent,
                  const float* __restrict__ memory,
                  const float* __restrict__ key,
                  const float* __restrict__ Wq, const float* __restrict__ bq,
                  const float* __restrict__ Wv, const float* __restrict__ bv,
                  const float* __restrict__ wg, const float* __restrict__ bg,
                  const float* __restrict__ wd, const float* __restrict__ bd,
                  const float* __restrict__ wp, const float* __restrict__ bp,
                  float* __restrict__ out)
{
    extern __shared__ char dynbuf[];
    __shared__ int   s_flag;
    __shared__ int   sti[4][Kn];
    __shared__ float stw[4][Kn];
    __shared__ float sgate[4];
    __shared__ float rd[Dn];
    __shared__ float r3[24];

    const int bid = blockIdx.x;
    const int tid = threadIdx.x;
    const float4* mem4 = (const float4*)memory;

    // ================= copy-only workers =================
    if (bid >= NWRK) {
        while (do_one_copy_tile(mem4, out)) {}
        __threadfence();
        __syncthreads();
        if (tid == 0) atomicAdd(&g_drained, 1);
        return;
    }

    // ================= compute workers (bid 0..127) =================

    // ---- Phase 1: qv tile (mat = bid>>6, 8 batches) ----
    {
        float4* sm = (float4*)dynbuf;               // 2048 float4 = 32KB
        const int mat = bid >> 6;
        const int b0  = (bid & 63) * 8;
        const float4* W4    = (const float4*)(mat ? Wv : Wq);
        const float4* bias4 = (const float4*)(mat ? bv : bq);
        float4*       out4  = mat ? g_value : g_query;

        const int dq = tid & 31;
        const int hs = tid >> 5;

        {
            const float4* src = (const float4*)(latent + (size_t)b0 * Hn);
            #pragma unroll
            for (int i = 0; i < 8; i++) sm[tid + i * 256] = src[tid + i * 256];
        }
        __syncthreads();

        float4 acc[8];
        #pragma unroll
        for (int j = 0; j < 8; j++) acc[j] = make_float4(0.f, 0.f, 0.f, 0.f);

        const int hbase = hs * 128;
        #pragma unroll 2
        for (int c = 0; c < 32; c++) {
            const int h0 = hbase + c * 4;
            float4 w0 = W4[(size_t)(h0 + 0) * 32 + dq];
            float4 w1 = W4[(size_t)(h0 + 1) * 32 + dq];
            float4 w2 = W4[(size_t)(h0 + 2) * 32 + dq];
            float4 w3 = W4[(size_t)(h0 + 3) * 32 + dq];
            #pragma unroll
            for (int j = 0; j < 8; j++) {
                float4 lf = sm[j * 256 + hs * 32 + c];
                acc[j].x += lf.x * w0.x + lf.y * w1.x + lf.z * w2.x + lf.w * w3.x;
                acc[j].y += lf.x * w0.y + lf.y * w1.y + lf.z * w2.y + lf.w * w3.y;
                acc[j].z += lf.x * w0.z + lf.y * w1.z + lf.z * w2.z + lf.w * w3.z;
                acc[j].w += lf.x * w0.w + lf.y * w1.w + lf.z * w2.w + lf.w * w3.w;
            }
        }
        __syncthreads();

        #pragma unroll
        for (int j = 0; j < 8; j++) sm[hs * 256 + j * 32 + dq] = acc[j];
        __syncthreads();

        {
            const int j2  = tid >> 5;
            const int dq2 = tid & 31;
            float4 s = make_float4(0.f, 0.f, 0.f, 0.f);
            #pragma unroll
            for (int h = 0; h < 8; h++) {
                float4 v = sm[h * 256 + j2 * 32 + dq2];
                s.x += v.x; s.y += v.y; s.z += v.z; s.w += v.w;
            }
            float4 bb = bias4[dq2];
            s.x += bb.x; s.y += bb.y; s.z += bb.z; s.w += bb.w;
            out4[(size_t)(b0 + j2) * 32 + dq2] = s;
        }
    }
    __threadfence();
    __syncthreads();
    if (tid == 0) atomicAdd(&g_qv_done, 1);

    // ---- steal copy tiles until all qv done ----
    for (;;) {
        if (tid == 0) s_flag = (atomicAdd(&g_qv_done, 0) >= NWRK);
        __syncthreads();
        if (s_flag) break;
        if (!do_one_copy_tile(mem4, out)) __nanosleep(100);
    }
    __threadfence();
    __syncthreads();

    // ---- Phase 2: logits, 4 tiles of 32b x 32s ----
    {
        float4* qs = (float4*)dynbuf;       // [32][33]
        float4* ks = qs + 32 * 33;          // [32][33]
        const float4* k4 = (const float4*)key;
        const int rb = tid >> 5;            // 0..7 (warp-uniform -> broadcast LDS)
        const int c  = tid & 31;

        for (int j = 0; j < 4; j++) {
            const int t  = bid + 128 * j;
            const int b0 = (t >> 5) * 32;
            const int s0 = (t & 31) * 32;
            __syncthreads();
            for (int i = tid; i < 1024; i += 256) {
                int r = i >> 5, cc = i & 31;
                qs[r * 33 + cc] = g_query[(size_t)(b0 + r) * 32 + cc];
                ks[r * 33 + cc] = k4[(size_t)(s0 + r) * 32 + cc];
            }
            __syncthreads();

            float a0 = 0.f, a1 = 0.f, a2 = 0.f, a3 = 0.f;
            #pragma unroll 8
            for (int c4 = 0; c4 < 32; c4++) {
                float4 kv = ks[c * 33 + c4];
                float4 q0 = qs[(rb     ) * 33 + c4];
                float4 q1 = qs[(rb +  8) * 33 + c4];
                float4 q2 = qs[(rb + 16) * 33 + c4];
                float4 q3 = qs[(rb + 24) * 33 + c4];
                a0 += q0.x*kv.x + q0.y*kv.y + q0.z*kv.z + q0.w*kv.w;
                a1 += q1.x*kv.x + q1.y*kv.y + q1.z*kv.z + q1.w*kv.w;
                a2 += q2.x*kv.x + q2.y*kv.y + q2.z*kv.z + q2.w*kv.w;
                a3 += q3.x*kv.x + q3.y*kv.y + q3.z*kv.z + q3.w*kv.w;
            }
            g_logits[(size_t)(b0 + rb     ) * Sn + s0 + c] = a0;
            g_logits[(size_t)(b0 + rb +  8) * Sn + s0 + c] = a1;
            g_logits[(size_t)(b0 + rb + 16) * Sn + s0 + c] = a2;
            g_logits[(size_t)(b0 + rb + 24) * Sn + s0 + c] = a3;
        }
    }
    __threadfence();
    __syncthreads();
    if (tid == 0) atomicAdd(&g_lg_done, 1);

    // ---- steal copy tiles until all logits done ----
    for (;;) {
        if (tid == 0) s_flag = (atomicAdd(&g_lg_done, 0) >= NWRK);
        __syncthreads();
        if (s_flag) break;
        if (!do_one_copy_tile(mem4, out)) __nanosleep(100);
    }
    __threadfence();
    __syncthreads();

    // ---- Phase 3: batch (4 batches per block) ----
    {
        float* sl = (float*)dynbuf;
        for (int j = 0; j < 4; j++) {
            const int b = bid + 128 * j;
            __syncthreads();
            for (int i = tid; i < Sn; i += 256) sl[i] = g_logits[(size_t)b * Sn + i];
            __syncthreads();

            if (tid < 32) {
                const int lane = tid;
                for (int it = 0; it < Kn; it++) {
                    float bv2 = -1e30f; int bi = 0;
                    #pragma unroll
                    for (int k = 0; k < 32; k++) {
                        float v = sl[lane + 32 * k];
                        if (v > bv2) { bv2 = v; bi = lane + 32 * k; }
                    }
                    #pragma unroll
                    for (int o = 16; o; o >>= 1) {
                        float ov = __shfl_xor_sync(0xffffffffu, bv2, o);
                        int   oi = __shfl_xor_sync(0xffffffffu, bi, o);
                        if (ov > bv2 || (ov == bv2 && oi < bi)) { bv2 = ov; bi = oi; }
                    }
                    if ((bi & 31) == lane) sl[bi] = -1e30f;
                    if (lane == 0) { sti[j][it] = bi; stw[j][it] = bv2; }
                    __syncwarp();
                }
                float m = stw[j][0];
                float e = __expf(stw[j][lane] - m);
                float s = e;
                #pragma unroll
                for (int o = 16; o; o >>= 1) s += __shfl_xor_sync(0xffffffffu, s, o);
                stw[j][lane] = e / s;
                __syncwarp();
            }
            __syncthreads();

            if (tid < Dn) {
                float acc = 0.f;
                #pragma unroll 8
                for (int k = 0; k < Kn; k++)
                    acc += stw[j][k] * memory[((size_t)b * Sn + sti[j][k]) * Dn + tid];
                out[READ_OFF + (size_t)b * Dn + tid] = acc;
                rd[tid] = acc;
            }
            __syncthreads();

            float pg = 0.f, pd = 0.f, pp = 0.f;
            const float* latb = latent + (size_t)b * Hn;
            for (int i = tid; i < Hn; i += 256) {
                float x = latb[i];
                pg += x * wg[i];
                pd += x * wd[i];
                pp += x * wp[i];
            }
            if (tid < Dn) {
                float x = rd[tid];
                pg += x * wg[Hn + tid];
                pd += x * wd[Hn + tid];
            }
            #pragma unroll
            for (int o = 16; o; o >>= 1) {
                pg += __shfl_xor_sync(0xffffffffu, pg, o);
                pd += __shfl_xor_sync(0xffffffffu, pd, o);
                pp += __shfl_xor_sync(0xffffffffu, pp, o);
            }
            const int wpid = tid >> 5, lane = tid & 31;
            if (lane == 0) { r3[wpid] = pg; r3[8 + wpid] = pd; r3[16 + wpid] = pp; }
            __syncthreads();
            if (tid == 0) {
                float G = 0.f, Dv = 0.f, P = 0.f;
                #pragma unroll
                for (int i = 0; i < 8; i++) { G += r3[i]; Dv += r3[8 + i]; P += r3[16 + i]; }
                float gate = 1.f / (1.f + __expf(-(G + bg[0])));
                float dmd  = tanhf(Dv + bd[0]);
                gate = gate * (0.75f + 0.5f * (dmd + 1.0f) * 0.5f);
                gate = fminf(fmaxf(gate, 0.f), 1.f);
                float ph = P + bp[0];
                gate *= 0.5f * (1.f + cosf(ph));
                sgate[j] = gate;
            }
            __syncthreads();
        }
    }

    // ---- Phase 4: join the copy pool ----
    while (do_one_copy_tile(mem4, out)) {}
    __threadfence();
    __syncthreads();
    if (tid == 0) atomicAdd(&g_drained, 1);

    // ---- global drain barrier, then fixup ----
    for (;;) {
        if (tid == 0) s_flag = (atomicAdd(&g_drained, 0) >= (int)gridDim.x);
        __syncthreads();
        if (s_flag) break;
        __nanosleep(200);
    }
    __threadfence();
    __syncthreads();

    {
        float4* dst = (float4*)(out + MEM_OFF);
        for (int j = 0; j < 4; j++) {
            const int b = bid + 128 * j;
            if (tid < Kn)
                out[W_OFF + (size_t)b * Sn + sti[j][tid]] = stw[j][tid];
            #pragma unroll
            for (int i = 0; i < 4; i++) {
                int idx = tid + i * 256;
                int r   = idx >> 5;
                int q   = idx & 31;
                int s   = sti[j][r];
                float w = sgate[j] * stw[j][r];
                size_t g = ((size_t)b * Sn + s) * 32 + q;
                float4 m = mem4[g];
                float4 v = g_value[b * 32 + q];
                m.x += w * (v.x - m.x);
                m.y += w * (v.y - m.y);
                m.z += w * (v.z - m.z);
                m.w += w * (v.w - m.w);
                dst[g] = m;
            }
        }
    }
}

// ---------------------------------------------------------------------------
extern "C" void kernel_launch(void* const* d_in, const int* in_sizes, int n_in,
                              void* d_out, int out_size)
{
    const float* latent    = (const float*)d_in[0];
    const float* memory    = (const float*)d_in[1];
    const float* rq_w      = (const float*)d_in[2];
    const float* rq_b      = (const float*)d_in[3];
    const float* mem_key   = (const float*)d_in[4];
    const float* wg_w      = (const float*)d_in[5];
    const float* wg_b      = (const float*)d_in[6];
    const float* wd_w      = (const float*)d_in[7];
    const float* wd_b      = (const float*)d_in[8];
    const float* wp_w      = (const float*)d_in[9];
    const float* wp_b      = (const float*)d_in[10];
    const float* wv_w      = (const float*)d_in[11];
    const float* wv_b      = (const float*)d_in[12];
    float* out = (float*)d_out;

    init_kernel<<<1, 1>>>();
    fused_kernel<<<NBLK, 256, DYN_SMEM>>>(latent, memory, mem_key,
                                          rq_w, rq_b, wv_w, wv_b,
                                          wg_w, wg_b, wd_w, wd_b, wp_w, wp_b,
                                          out);
}

// round 6
// speedup vs baseline: 1.0379x; 1.0379x over previous
#include <cuda_runtime.h>
#include <math.h>

#define Bn 512
#define Hn 1024
#define Sn 1024
#define Dn 128
#define Kn 32

// Output layout: [read (B*D)] [new_memory (B*S*D)] [weights (B*S)]
#define READ_OFF 0
#define MEM_OFF  (Bn*Dn)
#define W_OFF    (Bn*Dn + (size_t)Bn*Sn*Dn)

#define NCOPY 16384              // 16KB tiles of new_memory (1024 float4 each)
#define NZERO 128                // weights zero-fill tiles
#define NTOT  (NCOPY + NZERO)
#define NBLK  592                // 148 SMs x 4 resident CTAs
#define NWRK  128                // compute-role blocks
#define NCPB  (NBLK - NWRK)      // 464 copy-role blocks

// Scratch + sync state (no allocation allowed -> device globals)
__device__ float4 g_query[Bn * (Dn/4)];
__device__ float4 g_value[Bn * (Dn/4)];
__device__ float  g_logits[Bn * Sn];
__device__ int    g_qv_done, g_lg_done, g_drained;

#define DYN_SMEM 33792   // max(qv 32768, logits 33792, batch 4096)

__global__ void init_kernel()
{
    g_qv_done = 0; g_lg_done = 0; g_drained = 0;
}

// Consistent block-wide flag wait: double barrier so every thread reads the
// same published value (monotone 0->1 flags).
#define WAIT_FLAG(cond_expr)                                    \
    for (;;) {                                                  \
        if (threadIdx.x == 0) s_flag = (cond_expr);             \
        __syncthreads();                                        \
        int f_ = s_flag;                                        \
        __syncthreads();                                        \
        if (f_) break;                                          \
        __nanosleep(200);                                       \
    }

__global__ __launch_bounds__(256, 4)
void fused_kernel(const float* __restrict__ latent,
                  const float* __restrict__ memory,
                  const float* __restrict__ key,
                  const float* __restrict__ Wq, const float* __restrict__ bq,
                  const float* __restrict__ Wv, const float* __restrict__ bv,
                  const float* __restrict__ wg, const float* __restrict__ bg,
                  const float* __restrict__ wd, const float* __restrict__ bd,
                  const float* __restrict__ wp, const float* __restrict__ bp,
                  float* __restrict__ out)
{
    extern __shared__ char dynbuf[];
    __shared__ int   s_flag;
    __shared__ int   sti[4][Kn];
    __shared__ float stw[4][Kn];
    __shared__ float sgate[4];
    __shared__ float rd[Dn];
    __shared__ float r3[24];

    const int bid = blockIdx.x;
    const int tid = threadIdx.x;
    const float4* mem4 = (const float4*)memory;

    // ================= copy workers: static partition, no sync in loop ======
    if (bid >= NWRK) {
        const int c0 = bid - NWRK;
        float4* dstm = (float4*)(out + MEM_OFF);
        for (int t = c0; t < NCOPY; t += NCPB) {
            const float4* s = mem4 + (size_t)t * 1024;
            float4*       d = dstm + (size_t)t * 1024;
            #pragma unroll
            for (int j = 0; j < 4; j++) {
                int i = tid + j * 256;
                __stcs(&d[i], __ldcs(&s[i]));
            }
        }
        // weights zero-fill tiles (128 of them)
        if (c0 < NZERO) {
            float4* wz = (float4*)(out + W_OFF) + (size_t)c0 * 1024;
            float4 z = make_float4(0.f, 0.f, 0.f, 0.f);
            #pragma unroll
            for (int j = 0; j < 4; j++)
                __stcs(&wz[tid + j * 256], z);
        }
        __threadfence();
        __syncthreads();
        if (tid == 0) atomicAdd(&g_drained, 1);
        return;   // copy blocks never wait -> deadlock-free
    }

    // ================= compute workers (bid 0..127) =========================

    // ---- Phase 1: qv tile (mat = bid>>6, 8 batches each) ----
    {
        float4* sm = (float4*)dynbuf;               // 2048 float4 = 32KB
        const int mat = bid >> 6;
        const int b0  = (bid & 63) * 8;
        const float4* W4    = (const float4*)(mat ? Wv : Wq);
        const float4* bias4 = (const float4*)(mat ? bv : bq);
        float4*       out4  = mat ? g_value : g_query;

        const int dq = tid & 31;
        const int hs = tid >> 5;

        {
            const float4* src = (const float4*)(latent + (size_t)b0 * Hn);
            #pragma unroll
            for (int i = 0; i < 8; i++) sm[tid + i * 256] = src[tid + i * 256];
        }
        __syncthreads();

        float4 acc[8];
        #pragma unroll
        for (int j = 0; j < 8; j++) acc[j] = make_float4(0.f, 0.f, 0.f, 0.f);

        const int hbase = hs * 128;
        #pragma unroll 2
        for (int c = 0; c < 32; c++) {
            const int h0 = hbase + c * 4;
            float4 w0 = W4[(size_t)(h0 + 0) * 32 + dq];
            float4 w1 = W4[(size_t)(h0 + 1) * 32 + dq];
            float4 w2 = W4[(size_t)(h0 + 2) * 32 + dq];
            float4 w3 = W4[(size_t)(h0 + 3) * 32 + dq];
            #pragma unroll
            for (int j = 0; j < 8; j++) {
                float4 lf = sm[j * 256 + hs * 32 + c];
                acc[j].x += lf.x * w0.x + lf.y * w1.x + lf.z * w2.x + lf.w * w3.x;
                acc[j].y += lf.x * w0.y + lf.y * w1.y + lf.z * w2.y + lf.w * w3.y;
                acc[j].z += lf.x * w0.z + lf.y * w1.z + lf.z * w2.z + lf.w * w3.z;
                acc[j].w += lf.x * w0.w + lf.y * w1.w + lf.z * w2.w + lf.w * w3.w;
            }
        }
        __syncthreads();

        #pragma unroll
        for (int j = 0; j < 8; j++) sm[hs * 256 + j * 32 + dq] = acc[j];
        __syncthreads();

        {
            const int j2  = tid >> 5;
            const int dq2 = tid & 31;
            float4 s = make_float4(0.f, 0.f, 0.f, 0.f);
            #pragma unroll
            for (int h = 0; h < 8; h++) {
                float4 v = sm[h * 256 + j2 * 32 + dq2];
                s.x += v.x; s.y += v.y; s.z += v.z; s.w += v.w;
            }
            float4 bb = bias4[dq2];
            s.x += bb.x; s.y += bb.y; s.z += bb.z; s.w += bb.w;
            out4[(size_t)(b0 + j2) * 32 + dq2] = s;
        }
    }
    __threadfence();
    __syncthreads();
    if (tid == 0) atomicAdd(&g_qv_done, 1);

    WAIT_FLAG(atomicAdd(&g_qv_done, 0) >= NWRK);
    __threadfence();

    // ---- Phase 2: logits, 4 tiles of 32b x 32s ----
    {
        float4* qs = (float4*)dynbuf;       // [32][33]
        float4* ks = qs + 32 * 33;          // [32][33]
        const float4* k4 = (const float4*)key;
        const int rb = tid >> 5;            // warp-uniform -> broadcast LDS
        const int c  = tid & 31;

        for (int j = 0; j < 4; j++) {
            const int t  = bid + 128 * j;
            const int b0 = (t >> 5) * 32;
            const int s0 = (t & 31) * 32;
            __syncthreads();
            for (int i = tid; i < 1024; i += 256) {
                int r = i >> 5, cc = i & 31;
                qs[r * 33 + cc] = g_query[(size_t)(b0 + r) * 32 + cc];
                ks[r * 33 + cc] = k4[(size_t)(s0 + r) * 32 + cc];
            }
            __syncthreads();

            float a0 = 0.f, a1 = 0.f, a2 = 0.f, a3 = 0.f;
            #pragma unroll 8
            for (int c4 = 0; c4 < 32; c4++) {
                float4 kv = ks[c * 33 + c4];
                float4 q0 = qs[(rb     ) * 33 + c4];
                float4 q1 = qs[(rb +  8) * 33 + c4];
                float4 q2 = qs[(rb + 16) * 33 + c4];
                float4 q3 = qs[(rb + 24) * 33 + c4];
                a0 += q0.x*kv.x + q0.y*kv.y + q0.z*kv.z + q0.w*kv.w;
                a1 += q1.x*kv.x + q1.y*kv.y + q1.z*kv.z + q1.w*kv.w;
                a2 += q2.x*kv.x + q2.y*kv.y + q2.z*kv.z + q2.w*kv.w;
                a3 += q3.x*kv.x + q3.y*kv.y + q3.z*kv.z + q3.w*kv.w;
            }
            g_logits[(size_t)(b0 + rb     ) * Sn + s0 + c] = a0;
            g_logits[(size_t)(b0 + rb +  8) * Sn + s0 + c] = a1;
            g_logits[(size_t)(b0 + rb + 16) * Sn + s0 + c] = a2;
            g_logits[(size_t)(b0 + rb + 24) * Sn + s0 + c] = a3;
        }
    }
    __threadfence();
    __syncthreads();
    if (tid == 0) atomicAdd(&g_lg_done, 1);

    WAIT_FLAG(atomicAdd(&g_lg_done, 0) >= NWRK);
    __threadfence();

    // ---- Phase 3: batch (4 batches per block) ----
    {
        float* sl = (float*)dynbuf;
        for (int j = 0; j < 4; j++) {
            const int b = bid + 128 * j;
            __syncthreads();
            for (int i = tid; i < Sn; i += 256) sl[i] = g_logits[(size_t)b * Sn + i];
            __syncthreads();

            if (tid < 32) {
                const int lane = tid;
                for (int it = 0; it < Kn; it++) {
                    float bv2 = -1e30f; int bi = 0;
                    #pragma unroll
                    for (int k = 0; k < 32; k++) {
                        float v = sl[lane + 32 * k];
                        if (v > bv2) { bv2 = v; bi = lane + 32 * k; }
                    }
                    #pragma unroll
                    for (int o = 16; o; o >>= 1) {
                        float ov = __shfl_xor_sync(0xffffffffu, bv2, o);
                        int   oi = __shfl_xor_sync(0xffffffffu, bi, o);
                        if (ov > bv2 || (ov == bv2 && oi < bi)) { bv2 = ov; bi = oi; }
                    }
                    if ((bi & 31) == lane) sl[bi] = -1e30f;
                    if (lane == 0) { sti[j][it] = bi; stw[j][it] = bv2; }
                    __syncwarp();
                }
                float m = stw[j][0];
                float e = __expf(stw[j][lane] - m);
                float s = e;
                #pragma unroll
                for (int o = 16; o; o >>= 1) s += __shfl_xor_sync(0xffffffffu, s, o);
                stw[j][lane] = e / s;
                __syncwarp();
            }
            __syncthreads();

            if (tid < Dn) {
                float acc = 0.f;
                #pragma unroll 8
                for (int k = 0; k < Kn; k++)
                    acc += stw[j][k] * memory[((size_t)b * Sn + sti[j][k]) * Dn + tid];
                out[READ_OFF + (size_t)b * Dn + tid] = acc;
                rd[tid] = acc;
            }
            __syncthreads();

            float pg = 0.f, pd = 0.f, pp = 0.f;
            const float* latb = latent + (size_t)b * Hn;
            for (int i = tid; i < Hn; i += 256) {
                float x = latb[i];
                pg += x * wg[i];
                pd += x * wd[i];
                pp += x * wp[i];
            }
            if (tid < Dn) {
                float x = rd[tid];
                pg += x * wg[Hn + tid];
                pd += x * wd[Hn + tid];
            }
            #pragma unroll
            for (int o = 16; o; o >>= 1) {
                pg += __shfl_xor_sync(0xffffffffu, pg, o);
                pd += __shfl_xor_sync(0xffffffffu, pd, o);
                pp += __shfl_xor_sync(0xffffffffu, pp, o);
            }
            const int wpid = tid >> 5, lane = tid & 31;
            if (lane == 0) { r3[wpid] = pg; r3[8 + wpid] = pd; r3[16 + wpid] = pp; }
            __syncthreads();
            if (tid == 0) {
                float G = 0.f, Dv = 0.f, P = 0.f;
                #pragma unroll
                for (int i = 0; i < 8; i++) { G += r3[i]; Dv += r3[8 + i]; P += r3[16 + i]; }
                float gate = 1.f / (1.f + __expf(-(G + bg[0])));
                float dmd  = tanhf(Dv + bd[0]);
                gate = gate * (0.75f + 0.5f * (dmd + 1.0f) * 0.5f);
                gate = fminf(fmaxf(gate, 0.f), 1.f);
                float ph = P + bp[0];
                gate *= 0.5f * (1.f + cosf(ph));
                sgate[j] = gate;
            }
            __syncthreads();
        }
    }
    __threadfence();
    __syncthreads();
    if (tid == 0) atomicAdd(&g_drained, 1);

    // ---- drain barrier (all 592 blocks reported), then fixup ----
    WAIT_FLAG(atomicAdd(&g_drained, 0) >= NBLK);
    __threadfence();

    {
        float4* dst = (float4*)(out + MEM_OFF);
        for (int j = 0; j < 4; j++) {
            const int b = bid + 128 * j;
            if (tid < Kn)
                out[W_OFF + (size_t)b * Sn + sti[j][tid]] = stw[j][tid];
            #pragma unroll
            for (int i = 0; i < 4; i++) {
                int idx = tid + i * 256;
                int r   = idx >> 5;
                int q   = idx & 31;
                int s   = sti[j][r];
                float w = sgate[j] * stw[j][r];
                size_t g = ((size_t)b * Sn + s) * 32 + q;
                float4 m = mem4[g];
                float4 v = g_value[b * 32 + q];
                m.x += w * (v.x - m.x);
                m.y += w * (v.y - m.y);
                m.z += w * (v.z - m.z);
                m.w += w * (v.w - m.w);
                dst[g] = m;
            }
        }
    }
}

// ---------------------------------------------------------------------------
extern "C" void kernel_launch(void* const* d_in, const int* in_sizes, int n_in,
                              void* d_out, int out_size)
{
    const float* latent    = (const float*)d_in[0];
    const float* memory    = (const float*)d_in[1];
    const float* rq_w      = (const float*)d_in[2];
    const float* rq_b      = (const float*)d_in[3];
    const float* mem_key   = (const float*)d_in[4];
    const float* wg_w      = (const float*)d_in[5];
    const float* wg_b      = (const float*)d_in[6];
    const float* wd_w      = (const float*)d_in[7];
    const float* wd_b      = (const float*)d_in[8];
    const float* wp_w      = (const float*)d_in[9];
    const float* wp_b      = (const float*)d_in[10];
    const float* wv_w      = (const float*)d_in[11];
    const float* wv_b      = (const float*)d_in[12];
    float* out = (float*)d_out;

    init_kernel<<<1, 1>>>();
    fused_kernel<<<NBLK, 256, DYN_SMEM>>>(latent, memory, mem_key,
                                          rq_w, rq_b, wv_w, wv_b,
                                          wg_w, wg_b, wd_w, wd_b, wp_w, wp_b,
                                          out);
}